// round 3
// baseline (speedup 1.0000x reference)
#include <cuda_runtime.h>
#include <cuda_fp16.h>
#include <math.h>

#define B_  256
#define T_  512
#define S_  64
#define O_  128
#define H_  128
#define G4  512   // 4*H
#define BT_ ((size_t)B_ * T_)

// ---------------- scratch (device globals; no runtime allocation) ----------
__device__ __half g_gzh[BT_ * G4];         // 134 MB : obs@K + b (half)
__device__ __half g_hsh[BT_ * H_];         // 33.5 MB LSTM hidden (half)
__device__ __half g_pmh[BT_ * S_];         // 16.8 MB posterior mean (half)
__device__ float  g_ps [BT_ * S_];         // 33.5 MB posterior scale (fp32)
__device__ __half g_KTh [512 * 128];       // K^T  (n-major)
__device__ __half g_WrTh[128 * 128];       // [Wrm|Wrs]^T (n-major, n<64 mean)
__device__ __half g_WgTh[256 * 64];        // [Wgm|Wgs]^T (n-major, n<128 mean)
__device__ double g_acc[2];                // [0]=KL sum, [1]=recon-logp sum

__device__ __forceinline__ float softplusf_(float x) {
    return fmaxf(x, 0.f) + __logf(1.f + __expf(-fabsf(x)));
}
__device__ __forceinline__ float sigmf_(float x) {
    return __fdividef(1.f, 1.f + __expf(-x));
}
__device__ __forceinline__ float tanhfast_(float x) {
    return __fdividef(2.f, 1.f + __expf(-2.f * x)) - 1.f;
}

__device__ __forceinline__ void mma16816(float* c, const unsigned* a, const unsigned* b) {
    asm volatile(
        "mma.sync.aligned.m16n8k16.row.col.f32.f16.f16.f32 "
        "{%0,%1,%2,%3}, {%4,%5,%6,%7}, {%8,%9}, {%0,%1,%2,%3};\n"
        : "+f"(c[0]), "+f"(c[1]), "+f"(c[2]), "+f"(c[3])
        : "r"(a[0]), "r"(a[1]), "r"(a[2]), "r"(a[3]), "r"(b[0]), "r"(b[1]));
}

// ---------------------------------------------------------------------------
__global__ void k_zero() { if (threadIdx.x < 2) g_acc[threadIdx.x] = 0.0; }

// weight transposes/concats -> half
__global__ void k_prep_w(const float* __restrict__ K,  const float* __restrict__ Wrm,
                         const float* __restrict__ Wrs, const float* __restrict__ Wgm,
                         const float* __restrict__ Wgs) {
    int stride = gridDim.x * blockDim.x;
    for (int i = blockIdx.x * blockDim.x + threadIdx.x; i < 98304; i += stride) {
        if (i < 65536) {
            int n = i >> 7, k = i & 127;
            g_KTh[i] = __float2half(K[k * 512 + n]);
        } else if (i < 81920) {
            int j = i - 65536; int n = j >> 7, k = j & 127;
            float v = (n < 64) ? Wrm[k * 64 + n] : Wrs[k * 64 + (n - 64)];
            g_WrTh[j] = __float2half(v);
        } else {
            int j = i - 81920; int n = j >> 6, k = j & 63;
            float v = (n < 128) ? Wgm[k * 128 + n] : Wgs[k * 128 + (n - 128)];
            g_WgTh[j] = __float2half(v);
        }
    }
}

// ---------------------------------------------------------------------------
// gz = obs @ K + b via HMMA, output half.  grid (4, 1024), 256 thr.
__global__ __launch_bounds__(256) void k_xk(const float* __restrict__ obs,
                                            const float* __restrict__ bl) {
    extern __shared__ __half sm[];
    __half* As = sm;                 // [128][136]
    __half* Bt = sm + 128 * 136;     // [128][136]  (K^T tile: [n][k])
    const int tid = threadIdx.x;
    const int bt0 = blockIdx.y * 128;
    const int c0  = blockIdx.x * 128;

    const float4* ap = (const float4*)(obs + (size_t)bt0 * 128);
    #pragma unroll
    for (int i = tid; i < 128 * 32; i += 256) {
        int r = i >> 5, c = i & 31;
        float4 v = ap[r * 32 + c];
        *(half2*)&As[r * 136 + c * 4]     = __floats2half2_rn(v.x, v.y);
        *(half2*)&As[r * 136 + c * 4 + 2] = __floats2half2_rn(v.z, v.w);
    }
    const uint4* bp = (const uint4*)(g_KTh + (size_t)c0 * 128);
    #pragma unroll
    for (int i = tid; i < 128 * 16; i += 256) {
        int r = i >> 4, c = i & 15;
        *(uint4*)&Bt[r * 136 + c * 8] = bp[r * 16 + c];
    }
    __syncthreads();

    const int w = tid >> 5, l = tid & 31, g = l >> 2, tg = l & 3;
    const int m0 = w * 16;
    float acc[16][4];
    #pragma unroll
    for (int i = 0; i < 16; i++)
        #pragma unroll
        for (int j = 0; j < 4; j++) acc[i][j] = 0.f;

    #pragma unroll
    for (int kk = 0; kk < 8; kk++) {
        const int kb = kk * 16 + tg * 2;
        unsigned a[4];
        a[0] = *(const unsigned*)&As[(m0 + g)     * 136 + kb];
        a[1] = *(const unsigned*)&As[(m0 + g + 8) * 136 + kb];
        a[2] = *(const unsigned*)&As[(m0 + g)     * 136 + kb + 8];
        a[3] = *(const unsigned*)&As[(m0 + g + 8) * 136 + kb + 8];
        #pragma unroll
        for (int na = 0; na < 16; na++) {
            unsigned b[2];
            b[0] = *(const unsigned*)&Bt[(na * 8 + g) * 136 + kb];
            b[1] = *(const unsigned*)&Bt[(na * 8 + g) * 136 + kb + 8];
            mma16816(acc[na], a, b);
        }
    }
    #pragma unroll
    for (int na = 0; na < 16; na++) {
        int cc = c0 + na * 8 + tg * 2;
        float2 bb = *(const float2*)&bl[cc];
        size_t r0 = (size_t)(bt0 + m0 + g) * 512 + cc;
        *(half2*)&g_gzh[r0]           = __floats2half2_rn(acc[na][0] + bb.x, acc[na][1] + bb.y);
        *(half2*)&g_gzh[r0 + 8 * 512] = __floats2half2_rn(acc[na][2] + bb.x, acc[na][3] + bb.y);
    }
}

// ---------------------------------------------------------------------------
// LSTM recurrence: 128 blocks x 512 thr, 2 batch rows/block.
// Gate-permuted mapping: thread 4u+g owns gate column g*128+u -> the 4 gates
// of unit u sit in adjacent lanes; exchange via shfl, single sync per step.
__global__ __launch_bounds__(512, 1) void k_lstm(const float* __restrict__ R) {
    __shared__ __half hbuf[2][256];   // ping-pong [pp][r*128+u]
    const int tid = threadIdx.x;
    const int b0  = blockIdx.x * 2;
    const int g   = tid & 3, u = tid >> 2;      // u: 0..127
    const int col = g * 128 + u;                // gate column 0..511

    half2 wreg[64];
    #pragma unroll
    for (int j = 0; j < 64; j++)
        wreg[j] = __floats2half2_rn(R[(size_t)(2 * j) * 512 + col],
                                    R[(size_t)(2 * j + 1) * 512 + col]);
    ((__half*)hbuf)[tid] = __float2half(0.f);   // zero both buffers (512 halves)

    const __half* gz0 = g_gzh + (size_t)b0 * T_ * 512 + col;
    const __half* gz1 = gz0 + (size_t)T_ * 512;
    const bool writer = (g < 2);
    __half* hout = g_hsh + (size_t)(b0 + (g & 1)) * T_ * 128 + u;
    float cst = 0.f;

    float gv0 = __half2float(gz0[0]);
    float gv1 = __half2float(gz1[0]);
    __syncthreads();

    int pp = 0;
    for (int t = 0; t < T_; t++) {
        float ngv0 = 0.f, ngv1 = 0.f;
        if (t + 1 < T_) {
            ngv0 = __half2float(gz0[(size_t)(t + 1) * 512]);
            ngv1 = __half2float(gz1[(size_t)(t + 1) * 512]);
        }
        float fs0 = gv0, fs1 = gv1;
        const __half* hr = hbuf[pp];
        #pragma unroll
        for (int r = 0; r < 2; r++) {
            const uint4* hq = (const uint4*)(hr + r * 128);
            float acc = 0.f;
            #pragma unroll
            for (int cb = 0; cb < 4; cb++) {          // 4 chunks x 32 terms
                uint4 q0 = hq[cb * 4 + 0], q1 = hq[cb * 4 + 1];
                uint4 q2 = hq[cb * 4 + 2], q3 = hq[cb * 4 + 3];
                const half2* x0 = (const half2*)&q0;
                const half2* x1 = (const half2*)&q1;
                const half2* x2 = (const half2*)&q2;
                const half2* x3 = (const half2*)&q3;
                half2 a2 = __float2half2_rn(0.f);
                #pragma unroll
                for (int j = 0; j < 4; j++) a2 = __hfma2(wreg[cb * 16 + j],      x0[j], a2);
                #pragma unroll
                for (int j = 0; j < 4; j++) a2 = __hfma2(wreg[cb * 16 + 4 + j],  x1[j], a2);
                #pragma unroll
                for (int j = 0; j < 4; j++) a2 = __hfma2(wreg[cb * 16 + 8 + j],  x2[j], a2);
                #pragma unroll
                for (int j = 0; j < 4; j++) a2 = __hfma2(wreg[cb * 16 + 12 + j], x3[j], a2);
                float2 v = __half22float2(a2);
                acc += v.x + v.y;
            }
            if (r == 0) fs0 += acc; else fs1 += acc;
        }
        // butterfly within quads: gather all 4 gates of each row
        float b1r0 = __shfl_xor_sync(0xffffffffu, fs0, 1);
        float b2r0 = __shfl_xor_sync(0xffffffffu, fs0, 2);
        float b3r0 = __shfl_xor_sync(0xffffffffu, b1r0, 2);
        float b1r1 = __shfl_xor_sync(0xffffffffu, fs1, 1);
        float b2r1 = __shfl_xor_sync(0xffffffffu, fs1, 2);
        float b3r1 = __shfl_xor_sync(0xffffffffu, b1r1, 2);
        if (writer) {
            float vi, vf, vg, vo;
            if (g == 0) { vi = fs0;  vf = b1r0; vg = b2r0; vo = b3r0; }  // row 0
            else        { vi = b1r1; vf = fs1;  vg = b3r1; vo = b2r1; }  // row 1
            cst = sigmf_(vf) * cst + sigmf_(vi) * tanhfast_(vg);
            float hv = sigmf_(vo) * tanhfast_(cst);
            __half h16 = __float2half(hv);
            hbuf[pp ^ 1][g * 128 + u] = h16;
            hout[(size_t)t * 128] = h16;
        }
        __syncthreads();
        pp ^= 1;
        gv0 = ngv0; gv1 = ngv1;
    }
}

// ---------------------------------------------------------------------------
// heads: [hs]@[Wrm|Wrs] via HMMA.  grid 1024, 256 thr.  tile 128x128, k=128.
__global__ __launch_bounds__(256) void k_heads(const float* __restrict__ brm,
                                               const float* __restrict__ brs) {
    extern __shared__ __half sm[];
    __half* As = sm;                 // [128][136]
    __half* Bt = sm + 128 * 136;     // [128][136]
    const int tid = threadIdx.x;
    const int bt0 = blockIdx.x * 128;

    const uint4* ap = (const uint4*)(g_hsh + (size_t)bt0 * 128);
    const uint4* bp = (const uint4*)g_WrTh;
    #pragma unroll
    for (int i = tid; i < 128 * 16; i += 256) {
        int r = i >> 4, c = i & 15;
        *(uint4*)&As[r * 136 + c * 8] = ap[r * 16 + c];
        *(uint4*)&Bt[r * 136 + c * 8] = bp[r * 16 + c];
    }
    __syncthreads();

    const int w = tid >> 5, l = tid & 31, g = l >> 2, tg = l & 3;
    const int m0 = w * 16;
    float acc[16][4];
    #pragma unroll
    for (int i = 0; i < 16; i++)
        #pragma unroll
        for (int j = 0; j < 4; j++) acc[i][j] = 0.f;

    #pragma unroll
    for (int kk = 0; kk < 8; kk++) {
        const int kb = kk * 16 + tg * 2;
        unsigned a[4];
        a[0] = *(const unsigned*)&As[(m0 + g)     * 136 + kb];
        a[1] = *(const unsigned*)&As[(m0 + g + 8) * 136 + kb];
        a[2] = *(const unsigned*)&As[(m0 + g)     * 136 + kb + 8];
        a[3] = *(const unsigned*)&As[(m0 + g + 8) * 136 + kb + 8];
        #pragma unroll
        for (int na = 0; na < 16; na++) {
            unsigned b[2];
            b[0] = *(const unsigned*)&Bt[(na * 8 + g) * 136 + kb];
            b[1] = *(const unsigned*)&Bt[(na * 8 + g) * 136 + kb + 8];
            mma16816(acc[na], a, b);
        }
    }
    #pragma unroll
    for (int na = 0; na < 16; na++) {
        int cc = na * 8 + tg * 2;                 // 0..127 within concat
        int r0 = bt0 + m0 + g, r1 = r0 + 8;
        if (cc < 64) {
            float2 bm = *(const float2*)&brm[cc];
            *(half2*)&g_pmh[(size_t)r0 * 64 + cc] =
                __floats2half2_rn(acc[na][0] + bm.x, acc[na][1] + bm.y);
            *(half2*)&g_pmh[(size_t)r1 * 64 + cc] =
                __floats2half2_rn(acc[na][2] + bm.x, acc[na][3] + bm.y);
        } else {
            int c2 = cc - 64;
            float2 bs = *(const float2*)&brs[c2];
            *(float2*)&g_ps[(size_t)r0 * 64 + c2] =
                make_float2(softplusf_(acc[na][0] + bs.x), softplusf_(acc[na][1] + bs.y));
            *(float2*)&g_ps[(size_t)r1 * 64 + c2] =
                make_float2(softplusf_(acc[na][2] + bs.x), softplusf_(acc[na][3] + bs.y));
        }
    }
}

// ---------------------------------------------------------------------------
// generator + recon term via HMMA, fused reduction.  grid 1024, 512 thr.
__global__ __launch_bounds__(512) void k_gen(const float* __restrict__ obs,
                                             const float* __restrict__ bgm,
                                             const float* __restrict__ bgs) {
    extern __shared__ __half sm[];
    __half* As = sm;                 // [128][72]
    __half* Bt = sm + 128 * 72;      // [256][72]
    __shared__ float red[16];
    const int tid = threadIdx.x;
    const int bt0 = blockIdx.x * 128;

    const uint4* ap = (const uint4*)(g_pmh + (size_t)bt0 * 64);
    #pragma unroll
    for (int i = tid; i < 128 * 8; i += 512) {
        int r = i >> 3, c = i & 7;
        *(uint4*)&As[r * 72 + c * 8] = ap[r * 8 + c];
    }
    const uint4* bp = (const uint4*)g_WgTh;
    #pragma unroll
    for (int i = tid; i < 256 * 8; i += 512) {
        int r = i >> 3, c = i & 7;
        *(uint4*)&Bt[r * 72 + c * 8] = bp[i];
    }
    __syncthreads();

    const int w = tid >> 5, l = tid & 31, g = l >> 2, tg = l & 3;
    const int strip = w >> 1, ch = w & 1;
    const int m0 = strip * 16;
    float am[8][4], as_[8][4];
    #pragma unroll
    for (int i = 0; i < 8; i++)
        #pragma unroll
        for (int j = 0; j < 4; j++) { am[i][j] = 0.f; as_[i][j] = 0.f; }

    #pragma unroll
    for (int kk = 0; kk < 4; kk++) {
        const int kb = kk * 16 + tg * 2;
        unsigned a[4];
        a[0] = *(const unsigned*)&As[(m0 + g)     * 72 + kb];
        a[1] = *(const unsigned*)&As[(m0 + g + 8) * 72 + kb];
        a[2] = *(const unsigned*)&As[(m0 + g)     * 72 + kb + 8];
        a[3] = *(const unsigned*)&As[(m0 + g + 8) * 72 + kb + 8];
        #pragma unroll
        for (int na = 0; na < 8; na++) {
            int nmu = ch * 64 + na * 8 + g;
            unsigned b[2], b2[2];
            b[0]  = *(const unsigned*)&Bt[nmu * 72 + kb];
            b[1]  = *(const unsigned*)&Bt[nmu * 72 + kb + 8];
            b2[0] = *(const unsigned*)&Bt[(nmu + 128) * 72 + kb];
            b2[1] = *(const unsigned*)&Bt[(nmu + 128) * 72 + kb + 8];
            mma16816(am[na], a, b);
            mma16816(as_[na], a, b2);
        }
    }

    float lsum = 0.f;
    #pragma unroll
    for (int na = 0; na < 8; na++) {
        int oc = ch * 64 + na * 8 + tg * 2;
        float2 bm2 = *(const float2*)&bgm[oc];
        float2 bs2 = *(const float2*)&bgs[oc];
        int r0 = bt0 + m0 + g, r1 = r0 + 8;
        float2 o0 = *(const float2*)&obs[(size_t)r0 * 128 + oc];
        float2 o1 = *(const float2*)&obs[(size_t)r1 * 128 + oc];
        float mu, sg, d;
        mu = am[na][0] + bm2.x; sg = softplusf_(as_[na][0] + bs2.x);
        d = __fdividef(o0.x - mu, sg); lsum += -0.5f * d * d - __logf(sg);
        mu = am[na][1] + bm2.y; sg = softplusf_(as_[na][1] + bs2.y);
        d = __fdividef(o0.y - mu, sg); lsum += -0.5f * d * d - __logf(sg);
        mu = am[na][2] + bm2.x; sg = softplusf_(as_[na][2] + bs2.x);
        d = __fdividef(o1.x - mu, sg); lsum += -0.5f * d * d - __logf(sg);
        mu = am[na][3] + bm2.y; sg = softplusf_(as_[na][3] + bs2.y);
        d = __fdividef(o1.y - mu, sg); lsum += -0.5f * d * d - __logf(sg);
    }
    lsum -= 32.f * 0.91893853320467274f;   // 32 elements x 0.5*log(2pi)

    #pragma unroll
    for (int off = 16; off; off >>= 1) lsum += __shfl_down_sync(0xffffffffu, lsum, off);
    if (l == 0) red[w] = lsum;
    __syncthreads();
    if (tid == 0) {
        float s = 0.f;
        #pragma unroll
        for (int i = 0; i < 16; i++) s += red[i];
        atomicAdd(&g_acc[1], (double)s);
    }
}

// ---------------------------------------------------------------------------
// Prior rollout + KL. 256 blocks x 64 thr. Weights in half2 registers.
__global__ __launch_bounds__(64) void k_prior(const float* __restrict__ im,
                                              const float* __restrict__ Wfm,
                                              const float* __restrict__ bfm,
                                              const float* __restrict__ Wfs,
                                              const float* __restrict__ bfs) {
    __shared__ __half mh[64];
    __shared__ float red[2];
    const int s = threadIdx.x, b = blockIdx.x;

    half2 wm[32], ws[32];
    #pragma unroll
    for (int j = 0; j < 32; j++) {
        wm[j] = __floats2half2_rn(Wfm[(2 * j) * 64 + s], Wfm[(2 * j + 1) * 64 + s]);
        ws[j] = __floats2half2_rn(Wfs[(2 * j) * 64 + s], Wfs[(2 * j + 1) * 64 + s]);
    }
    mh[s] = __float2half(im[b * 64 + s]);
    const float bmv = bfm[s], bsv = bfs[s];
    __syncthreads();

    const __half* pmp = g_pmh + (size_t)b * T_ * 64 + s;
    const float*  psp = g_ps  + (size_t)b * T_ * 64 + s;
    float pmv = __half2float(pmp[0]);
    float psv = psp[0];

    float klsum = 0.f;
    for (int t = 0; t < T_; t++) {
        float npm = 0.f, nps = 1.f;
        if (t + 1 < T_) {
            npm = __half2float(pmp[(size_t)(t + 1) * 64]);
            nps = psp[(size_t)(t + 1) * 64];
        }
        float amv = bmv, asv = bsv;
        const uint4* m4 = (const uint4*)mh;
        #pragma unroll
        for (int cb = 0; cb < 2; cb++) {         // 2 chunks x 32 terms
            uint4 q0 = m4[cb * 4 + 0], q1 = m4[cb * 4 + 1];
            uint4 q2 = m4[cb * 4 + 2], q3 = m4[cb * 4 + 3];
            const half2* x0 = (const half2*)&q0;
            const half2* x1 = (const half2*)&q1;
            const half2* x2 = (const half2*)&q2;
            const half2* x3 = (const half2*)&q3;
            half2 am2 = __float2half2_rn(0.f), as2 = am2;
            #pragma unroll
            for (int j = 0; j < 4; j++) {
                am2 = __hfma2(wm[cb * 16 + j],      x0[j], am2);
                as2 = __hfma2(ws[cb * 16 + j],      x0[j], as2);
                am2 = __hfma2(wm[cb * 16 + 4 + j],  x1[j], am2);
                as2 = __hfma2(ws[cb * 16 + 4 + j],  x1[j], as2);
                am2 = __hfma2(wm[cb * 16 + 8 + j],  x2[j], am2);
                as2 = __hfma2(ws[cb * 16 + 8 + j],  x2[j], as2);
                am2 = __hfma2(wm[cb * 16 + 12 + j], x3[j], am2);
                as2 = __hfma2(ws[cb * 16 + 12 + j], x3[j], as2);
            }
            float2 v;
            v = __half22float2(am2); amv += v.x + v.y;
            v = __half22float2(as2); asv += v.x + v.y;
        }
        float sn = softplusf_(asv);
        float d  = pmv - amv;
        klsum += __logf(__fdividef(sn, psv))
               + __fdividef(psv * psv + d * d, 2.f * sn * sn) - 0.5f;
        __syncthreads();
        mh[s] = __float2half(amv);
        __syncthreads();
        pmv = npm; psv = nps;
    }
    #pragma unroll
    for (int off = 16; off; off >>= 1) klsum += __shfl_down_sync(0xffffffffu, klsum, off);
    if ((s & 31) == 0) red[s >> 5] = klsum;
    __syncthreads();
    if (s == 0) atomicAdd(&g_acc[0], (double)(red[0] + red[1]));
}

// ---------------------------------------------------------------------------
__global__ void k_fin(float* out) {
    out[0] = (float)(g_acc[0] / (double)BT_ - g_acc[1] / (double)B_);
}

// ---------------------------------------------------------------------------
extern "C" void kernel_launch(void* const* d_in, const int* in_sizes, int n_in,
                              void* d_out, int out_size) {
    const float* obs = (const float*)d_in[0];
    const float* im  = (const float*)d_in[1];
    // d_in[2] = initial_scale (unused by the reference computation)
    const float* Wfm = (const float*)d_in[3];
    const float* bfm = (const float*)d_in[4];
    const float* Wfs = (const float*)d_in[5];
    const float* bfs = (const float*)d_in[6];
    const float* Wgm = (const float*)d_in[7];
    const float* bgm = (const float*)d_in[8];
    const float* Wgs = (const float*)d_in[9];
    const float* bgs = (const float*)d_in[10];
    const float* K   = (const float*)d_in[11];
    const float* R   = (const float*)d_in[12];
    const float* bl  = (const float*)d_in[13];
    const float* Wrm = (const float*)d_in[14];
    const float* brm = (const float*)d_in[15];
    const float* Wrs = (const float*)d_in[16];
    const float* brs = (const float*)d_in[17];
    float* out = (float*)d_out;

    const int GEMM_SM = 2 * 128 * 136 * 2;          // 69632
    const int GEN_SM  = (128 * 72 + 256 * 72) * 2;  // 55296
    cudaFuncSetAttribute(k_xk,    cudaFuncAttributeMaxDynamicSharedMemorySize, GEMM_SM);
    cudaFuncSetAttribute(k_heads, cudaFuncAttributeMaxDynamicSharedMemorySize, GEMM_SM);
    cudaFuncSetAttribute(k_gen,   cudaFuncAttributeMaxDynamicSharedMemorySize, GEN_SM);

    k_zero<<<1, 32>>>();
    k_prep_w<<<128, 256>>>(K, Wrm, Wrs, Wgm, Wgs);
    k_xk<<<dim3(4, 1024), 256, GEMM_SM>>>(obs, bl);
    k_lstm<<<128, 512>>>(R);
    k_heads<<<1024, 256, GEMM_SM>>>(brm, brs);
    k_gen<<<1024, 512, GEN_SM>>>(obs, bgm, bgs);
    k_prior<<<256, 64>>>(im, Wfm, bfm, Wfs, bfs);
    k_fin<<<1, 1>>>(out);
}